// round 13
// baseline (speedup 1.0000x reference)
#include <cuda_runtime.h>
#include <cuda_bf16.h>
#include <cstdint>

// ---------------------------------------------------------------------------
// Problem constants
// ---------------------------------------------------------------------------
#define DD    101                 // inner dim
#define KO    101                 // output cols
#define KPAD  104                 // 13 * 8
#define BM    64                  // batch rows per tile
#define NGRP  4                   // compute groups (4 warps each)
#define NSLOT 7                   // ring slots
#define NTHR  (NGRP * 128 + 32)   // 544: 16 compute warps + 1 producer warp

// B image: [kt][n][tg] float2 pairs = (A[k0+tg][n], A[k0+tg+4][n])
#define A_IMG_BYTES (13 * KPAD * 4 * 8)   // 43264

#define TILE_BYTES (BM * DD * 4)          // 25856 (slot size, exact)

// smem layout (bytes): [A][7 slots][256 zero pad][mbars]
#define AIMG_OFF 0
#define RAWBASE  A_IMG_BYTES                       // 43264
#define PAD_OFF  (RAWBASE + NSLOT * TILE_BYTES)    // 224256
#define MBAR_OFF (PAD_OFF + 256)                   // 224512
// full[7] @ +0, empty[7] @ +56, A @ +112
#define SMEM_BYTES 224640

#define GRID 148                          // 1 CTA/SM; CTA b owns tiles b+148c

__device__ __align__(16) unsigned char g_Apair[A_IMG_BYTES];

// ---------------------------------------------------------------------------
// Helpers
// ---------------------------------------------------------------------------
__device__ __forceinline__ uint32_t smem_u32(const void* p) {
    uint32_t a;
    asm("{ .reg .u64 t; cvta.to.shared.u64 t, %1; cvt.u32.u64 %0, t; }"
        : "=r"(a) : "l"(p));
    return a;
}
__device__ __forceinline__ void mbar_init(uint32_t m, uint32_t cnt) {
    asm volatile("mbarrier.init.shared.b64 [%0], %1;" :: "r"(m), "r"(cnt) : "memory");
}
__device__ __forceinline__ void mbar_arrive(uint32_t m) {
    asm volatile("mbarrier.arrive.shared.b64 _, [%0];" :: "r"(m) : "memory");
}
__device__ __forceinline__ void mbar_expect_tx(uint32_t m, uint32_t bytes) {
    asm volatile("mbarrier.arrive.expect_tx.shared.b64 _, [%0], %1;"
                 :: "r"(m), "r"(bytes) : "memory");
}
__device__ __forceinline__ void mbar_wait(uint32_t m, uint32_t parity) {
    asm volatile(
        "{\n\t.reg .pred P;\n"
        "W_%=:\n\t"
        "mbarrier.try_wait.parity.acquire.cta.shared::cta.b64 P, [%0], %1;\n\t"
        "@!P bra W_%=;\n\t}"
        :: "r"(m), "r"(parity) : "memory");
}
__device__ __forceinline__ void bulk_g2s(uint32_t dst, const void* src,
                                         uint32_t bytes, uint32_t m) {
    asm volatile(
        "cp.async.bulk.shared::cta.global.mbarrier::complete_tx::bytes "
        "[%0], [%1], %2, [%3];"
        :: "r"(dst), "l"(src), "r"(bytes), "r"(m) : "memory");
}
__device__ __forceinline__ void bulk_s2g(void* gdst, uint32_t ssrc, uint32_t bytes) {
    asm volatile("cp.async.bulk.global.shared::cta.bulk_group [%0], [%1], %2;"
                 :: "l"(gdst), "r"(ssrc), "r"(bytes) : "memory");
}
#define S2G_COMMIT() asm volatile("cp.async.bulk.commit_group;" ::: "memory")
#define S2G_WAIT0()  asm volatile("cp.async.bulk.wait_group 0;" ::: "memory")
#define GRP_BAR(id)  asm volatile("bar.sync %0, 128;" :: "r"(id) : "memory")
#define FENCE_ASYNC() asm volatile("fence.proxy.async.shared::cta;" ::: "memory")

__device__ __forceinline__ float ldsf(uint32_t a) {
    float v;
    asm volatile("ld.shared.f32 %0, [%1];" : "=f"(v) : "r"(a));
    return v;
}
__device__ __forceinline__ void ldsv2(uint32_t* r, uint32_t a) {
    asm volatile("ld.shared.v2.b32 {%0,%1}, [%2];"
                 : "=r"(r[0]), "=r"(r[1]) : "r"(a));
}
__device__ __forceinline__ void stsf(uint32_t a, float v) {
    asm volatile("st.shared.f32 [%0], %1;" :: "r"(a), "f"(v) : "memory");
}
__device__ __forceinline__ uint32_t to_tf32(float f) {
    uint32_t r;
    asm("cvt.rna.tf32.f32 %0, %1;" : "=r"(r) : "f"(f));
    return r;
}
__device__ __forceinline__ void mma_tf32(float* c, const uint32_t* a,
                                         const uint32_t* b) {
    asm volatile(
        "mma.sync.aligned.m16n8k8.row.col.f32.tf32.tf32.f32 "
        "{%0,%1,%2,%3}, {%4,%5,%6,%7}, {%8,%9}, {%0,%1,%2,%3};"
        : "+f"(c[0]), "+f"(c[1]), "+f"(c[2]), "+f"(c[3])
        : "r"(a[0]), "r"(a[1]), "r"(a[2]), "r"(a[3]), "r"(b[0]), "r"(b[1]));
}

// ---------------------------------------------------------------------------
// Kernel 1 (closed form): ReJ/ImJ are sparse selections, so
//   A[n,d] = ( Wre[n,d] + [d>=1]*Wre[n,101-d] ) / 101          d <= 50
//   A[n,d] = ( Wim[n,151-d] - Wim[n,d-50] ) / 101              51 <= d <= 100
// stored tf32-rounded into the frag-pair image
//   g_Apair[kt][n][tg] = ( A[kt*8+tg][n], A[kt*8+tg+4][n] )
// ---------------------------------------------------------------------------
__global__ void build_A_kernel(const float* __restrict__ Wre,
                               const float* __restrict__ Wim) {
    const int n = blockIdx.x;       // 0..103
    const int d = threadIdx.x;      // 0..103
    float a = 0.0f;
    if (n < KO && d < DD) {
        if (d <= 50) {
            a = Wre[n * DD + d];
            if (d >= 1) a += Wre[n * DD + (101 - d)];
        } else {
            a = Wim[n * DD + (151 - d)] - Wim[n * DD + (d - 50)];
        }
        a *= (1.0f / 101.0f);
    }
    const int kt   = d >> 3;
    const int r    = d & 7;
    const int tg   = r & 3;
    const int slot = r >> 2;
    *(uint32_t*)(g_Apair + kt * 3328 + n * 32 + tg * 8 + slot * 4) = to_tf32(a);
}

// ---------------------------------------------------------------------------
// Kernel 2: ring-buffer persistent GEMM.
//   warp 16 (1 elected thread) = producer: streams tiles c=0.. into slot c%7.
//   groups 0..3 (4 warps each)  = consumers: group g computes c == g (mod 4);
//     per tile: wait full -> MMA mainloop -> stage -> TMA out -> drain ->
//     arrive empty.
// Compute core identical to the R11/R12 winner (M=32 warp tiles, permuted
// conflict-free a-loads, paired-B LDS.64).
// ---------------------------------------------------------------------------
extern __shared__ unsigned char smem[];

__global__ void __launch_bounds__(NTHR, 1)
fourier_mma_kernel(const float* __restrict__ x, float* __restrict__ out,
                   int ntiles) {
    const int tid   = threadIdx.x;
    const int wid   = tid >> 5;       // 0..16
    const int grp   = tid >> 7;       // 0..3 for consumers, 4 for producer
    const int gtid  = tid & 127;
    const int w4    = (tid >> 5) & 3;
    const int lane  = tid & 31;
    const int g     = lane >> 2;
    const int tg    = lane & 3;
    const int mwarp = w4 >> 1;
    const int nhalf = w4 & 1;
    const int NT    = nhalf ? 6 : 7;
    const uint32_t sbase = smem_u32(smem);
    const uint32_t mbF = sbase + MBAR_OFF;        // full[7]
    const uint32_t mbE = sbase + MBAR_OFF + 56;   // empty[7]
    const uint32_t mbA = sbase + MBAR_OFF + 112;

    // number of local tiles for this CTA: tiles t = bid + 148*c
    const int climit = (ntiles - (int)blockIdx.x + GRID - 1) / GRID;

    // zero-fill all slots + pad (finite data everywhere before first MMA)
    for (int i = tid; i < (NSLOT * TILE_BYTES + 256) / 4; i += NTHR)
        *(uint32_t*)(smem + RAWBASE + i * 4) = 0;
    if (tid == 0) {
        #pragma unroll
        for (int i = 0; i < NSLOT; ++i) {
            mbar_init(mbF + i * 8, 1);
            mbar_init(mbE + i * 8, 1);
        }
        mbar_init(mbA, 1);
        mbar_expect_tx(mbA, A_IMG_BYTES);
        bulk_g2s(sbase + AIMG_OFF, g_Apair, A_IMG_BYTES, mbA);
    }
    __syncthreads();               // zeros + mbar inits visible

    // ---- producer warp ----
    if (wid == 16) {
        if (lane == 0) {
            FENCE_ASYNC();         // order zero-fill before TMA overwrites
            const char* xb = (const char*)x + (size_t)blockIdx.x * TILE_BYTES;
            #pragma unroll 1
            for (int c = 0; c < climit; ++c) {
                const int s = c % NSLOT;
                const int k = c / NSLOT;
                if (k > 0) mbar_wait(mbE + s * 8, (uint32_t)((k - 1) & 1));
                mbar_expect_tx(mbF + s * 8, TILE_BYTES);
                bulk_g2s(sbase + RAWBASE + (uint32_t)s * TILE_BYTES,
                         xb + (size_t)c * (GRID * TILE_BYTES),
                         TILE_BYTES, mbF + s * 8);
            }
        }
        return;                    // producer warp done issuing
    }

    // ---- consumers ----
    mbar_wait(mbA, 0);             // A panel resident

    // a-frag bases: frag f, row = (2m+f) + 4g, k word = tg (conflict-free)
    const uint32_t ra0 = (uint32_t)(((2 * mwarp + 0) + 4 * g) * DD + tg) * 4u;
    const uint32_t ra1 = (uint32_t)(((2 * mwarp + 1) + 4 * g) * DD + tg) * 4u;
    // b pair base: [kt=0][n = nhalf*56 + g][tg]
    const uint32_t rbA = sbase + AIMG_OFF
        + (uint32_t)((nhalf * 56 + g) * 32 + tg * 8);
    const int barid = grp + 1;

    #pragma unroll 1
    for (int c = grp; c < climit; c += NGRP) {
        const int s = c % NSLOT;
        const int k = c / NSLOT;
        mbar_wait(mbF + s * 8, (uint32_t)(k & 1));

        float acc[2][7][4];
        #pragma unroll
        for (int f = 0; f < 2; ++f)
            #pragma unroll
            for (int nt = 0; nt < 7; ++nt)
                #pragma unroll
                for (int i = 0; i < 4; ++i) acc[f][nt][i] = 0.0f;

        const uint32_t rawb = sbase + RAWBASE + (uint32_t)s * TILE_BYTES;
        const uint32_t rx0 = rawb + ra0;
        const uint32_t rx1 = rawb + ra1;

        #pragma unroll
        for (int kt = 0; kt < 13; ++kt) {
            const uint32_t ko = (uint32_t)kt * 32u;
            uint32_t a0[4], a1[4];
            a0[0] = to_tf32(ldsf(rx0 + ko));
            a0[1] = to_tf32(ldsf(rx0 + ko + 12928));       // +32 rows
            a0[2] = to_tf32(ldsf(rx0 + ko + 16));          // +4 k cols
            a0[3] = to_tf32(ldsf(rx0 + ko + 12928 + 16));
            a1[0] = to_tf32(ldsf(rx1 + ko));
            a1[1] = to_tf32(ldsf(rx1 + ko + 12928));
            a1[2] = to_tf32(ldsf(rx1 + ko + 16));
            a1[3] = to_tf32(ldsf(rx1 + ko + 12928 + 16));

            const uint32_t kb = rbA + (uint32_t)kt * 3328u;
            uint32_t b[7][2];
            #pragma unroll
            for (int nt = 0; nt < 7; ++nt)
                if (nt < NT) ldsv2(b[nt], kb + (uint32_t)nt * 256u);

            #pragma unroll
            for (int nt = 0; nt < 7; ++nt)
                if (nt < NT) mma_tf32(acc[0][nt], a0, b[nt]);
            #pragma unroll
            for (int nt = 0; nt < 7; ++nt)
                if (nt < NT) mma_tf32(acc[1][nt], a1, b[nt]);
        }

        // ---- epilogue: stage [64 x 101] fp32 image back into the slot ----
        GRP_BAR(barid);    // all 4 warps done reading this slot's x
        {
            #pragma unroll
            for (int f = 0; f < 2; ++f) {
                const uint32_t st0 = rawb
                    + (uint32_t)(((2 * mwarp + f) + 4 * g) * KO) * 4u;
                #pragma unroll
                for (int nt = 0; nt < 7; ++nt) {
                    if (nt >= NT) break;
                    const int col = nhalf * 56 + nt * 8 + tg * 2;
                    if (col < KO) {
                        stsf(st0 + (uint32_t)col * 4u, acc[f][nt][0]);
                        stsf(st0 + 12928u + (uint32_t)col * 4u, acc[f][nt][2]);
                        if (col + 1 < KO) {
                            stsf(st0 + (uint32_t)(col + 1) * 4u, acc[f][nt][1]);
                            stsf(st0 + 12928u + (uint32_t)(col + 1) * 4u,
                                 acc[f][nt][3]);
                        }
                    }
                }
            }
        }
        GRP_BAR(barid);    // tile fully staged (bar.sync drains STS)
        if (gtid == 0) {
            const int t = (int)blockIdx.x + GRID * c;
            FENCE_ASYNC();
            bulk_s2g(out + (size_t)t * (BM * KO), rawb, TILE_BYTES);
            S2G_COMMIT();
            S2G_WAIT0();           // drain, then hand the slot back
            mbar_arrive(mbE + s * 8);
        }
    }
}

// ---------------------------------------------------------------------------
// Launch
// ---------------------------------------------------------------------------
extern "C" void kernel_launch(void* const* d_in, const int* in_sizes, int n_in,
                              void* d_out, int out_size) {
    const float* x   = (const float*)d_in[0];
    const float* Wre = (const float*)d_in[1];
    const float* Wim = (const float*)d_in[2];
    float* out = (float*)d_out;

    const int B = in_sizes[0] / DD;       // 262144
    const int ntiles = B / BM;            // 4096

    build_A_kernel<<<KPAD, KPAD>>>(Wre, Wim);

    cudaFuncSetAttribute(fourier_mma_kernel,
                         cudaFuncAttributeMaxDynamicSharedMemorySize, SMEM_BYTES);
    fourier_mma_kernel<<<GRID, NTHR, SMEM_BYTES>>>(x, out, ntiles);
    (void)n_in; (void)out_size;
}

// round 14
// speedup vs baseline: 1.0952x; 1.0952x over previous
#include <cuda_runtime.h>
#include <cuda_fp16.h>
#include <cstdint>

// ---------------------------------------------------------------------------
// Problem constants
// ---------------------------------------------------------------------------
#define DD    101                 // inner dim
#define KO    101                 // output cols
#define KPAD2 112                 // 7 * 16 (fp16 k16 steps)
#define BM    64                  // batch rows per tile
#define NGRP  4                   // compute groups (4 warps each)
#define NSLOT 7                   // ring slots
#define NTHR  (NGRP * 128 + 32)   // 544

// B image (fp16): [kt][n][tg] -> two words:
//   w0 = half2( A[k0+2tg][n],   A[k0+2tg+1][n] )
//   w1 = half2( A[k0+2tg+8][n], A[k0+2tg+9][n] ),  k0 = kt*16
#define A_IMG_BYTES (7 * 104 * 4 * 8)     // 23296

#define TILE_BYTES (BM * DD * 4)          // 25856 (slot size, exact)

// smem layout (bytes): [A][7 slots][256 zero pad][mbars]
#define AIMG_OFF 0
#define RAWBASE  A_IMG_BYTES                       // 23296
#define PAD_OFF  (RAWBASE + NSLOT * TILE_BYTES)    // 204288
#define MBAR_OFF (PAD_OFF + 256)                   // 204544
#define SMEM_BYTES 204672

#define GRID 148                          // 1 CTA/SM; CTA b owns tiles b+148c

__device__ __align__(16) unsigned char g_Apair[A_IMG_BYTES];

// ---------------------------------------------------------------------------
// Helpers
// ---------------------------------------------------------------------------
__device__ __forceinline__ uint32_t smem_u32(const void* p) {
    uint32_t a;
    asm("{ .reg .u64 t; cvta.to.shared.u64 t, %1; cvt.u32.u64 %0, t; }"
        : "=r"(a) : "l"(p));
    return a;
}
__device__ __forceinline__ void mbar_init(uint32_t m, uint32_t cnt) {
    asm volatile("mbarrier.init.shared.b64 [%0], %1;" :: "r"(m), "r"(cnt) : "memory");
}
__device__ __forceinline__ void mbar_arrive(uint32_t m) {
    asm volatile("mbarrier.arrive.shared.b64 _, [%0];" :: "r"(m) : "memory");
}
__device__ __forceinline__ void mbar_expect_tx(uint32_t m, uint32_t bytes) {
    asm volatile("mbarrier.arrive.expect_tx.shared.b64 _, [%0], %1;"
                 :: "r"(m), "r"(bytes) : "memory");
}
__device__ __forceinline__ void mbar_wait(uint32_t m, uint32_t parity) {
    asm volatile(
        "{\n\t.reg .pred P;\n"
        "W_%=:\n\t"
        "mbarrier.try_wait.parity.acquire.cta.shared::cta.b64 P, [%0], %1;\n\t"
        "@!P bra W_%=;\n\t}"
        :: "r"(m), "r"(parity) : "memory");
}
__device__ __forceinline__ void bulk_g2s(uint32_t dst, const void* src,
                                         uint32_t bytes, uint32_t m) {
    asm volatile(
        "cp.async.bulk.shared::cta.global.mbarrier::complete_tx::bytes "
        "[%0], [%1], %2, [%3];"
        :: "r"(dst), "l"(src), "r"(bytes), "r"(m) : "memory");
}
__device__ __forceinline__ void bulk_s2g(void* gdst, uint32_t ssrc, uint32_t bytes) {
    asm volatile("cp.async.bulk.global.shared::cta.bulk_group [%0], [%1], %2;"
                 :: "l"(gdst), "r"(ssrc), "r"(bytes) : "memory");
}
#define S2G_COMMIT() asm volatile("cp.async.bulk.commit_group;" ::: "memory")
#define S2G_WAIT0()  asm volatile("cp.async.bulk.wait_group 0;" ::: "memory")
#define GRP_BAR(id)  asm volatile("bar.sync %0, 128;" :: "r"(id) : "memory")
#define FENCE_ASYNC() asm volatile("fence.proxy.async.shared::cta;" ::: "memory")

__device__ __forceinline__ float ldsf(uint32_t a) {
    float v;
    asm volatile("ld.shared.f32 %0, [%1];" : "=f"(v) : "r"(a));
    return v;
}
__device__ __forceinline__ void ldsv2(uint32_t* r, uint32_t a) {
    asm volatile("ld.shared.v2.b32 {%0,%1}, [%2];"
                 : "=r"(r[0]), "=r"(r[1]) : "r"(a));
}
__device__ __forceinline__ void stsf(uint32_t a, float v) {
    asm volatile("st.shared.f32 [%0], %1;" :: "r"(a), "f"(v) : "memory");
}
// pack two f32 -> f16x2 (lo = first arg position per PTX: d = {hiSrc, loSrc})
__device__ __forceinline__ uint32_t pack_h2(float lo, float hi) {
    uint32_t r;
    asm("cvt.rn.f16x2.f32 %0, %1, %2;" : "=r"(r) : "f"(hi), "f"(lo));
    return r;
}
__device__ __forceinline__ void mma_f16(float* c, const uint32_t* a,
                                        const uint32_t* b) {
    asm volatile(
        "mma.sync.aligned.m16n8k16.row.col.f32.f16.f16.f32 "
        "{%0,%1,%2,%3}, {%4,%5,%6,%7}, {%8,%9}, {%0,%1,%2,%3};"
        : "+f"(c[0]), "+f"(c[1]), "+f"(c[2]), "+f"(c[3])
        : "r"(a[0]), "r"(a[1]), "r"(a[2]), "r"(a[3]), "r"(b[0]), "r"(b[1]));
}

// ---------------------------------------------------------------------------
// Kernel 1 (closed form): ReJ/ImJ are sparse selections, so
//   A[n,d] = ( Wre[n,d] + [d>=1]*Wre[n,101-d] ) / 101          d <= 50
//   A[n,d] = ( Wim[n,151-d] - Wim[n,d-50] ) / 101              51 <= d <= 100
// stored fp16 into the k16 frag-pair image (see layout at A_IMG_BYTES).
// grid: n = 0..103; threads: d = 0..111.
// ---------------------------------------------------------------------------
__global__ void build_A_kernel(const float* __restrict__ Wre,
                               const float* __restrict__ Wim) {
    const int n = blockIdx.x;       // 0..103
    const int d = threadIdx.x;      // 0..111
    float a = 0.0f;
    if (n < KO && d < DD) {
        if (d <= 50) {
            a = Wre[n * DD + d];
            if (d >= 1) a += Wre[n * DD + (101 - d)];
        } else {
            a = Wim[n * DD + (151 - d)] - Wim[n * DD + (d - 50)];
        }
        a *= (1.0f / 101.0f);
    }
    const int kt   = d >> 4;        // 0..6
    const int r    = d & 15;
    const int slot = r >> 3;        // 0: k0+2tg{+1}, 1: k0+2tg+8{+1}
    const int rr   = r & 7;
    const int tg   = rr >> 1;
    const int o    = rr & 1;        // lo/hi half of the word
    const uint32_t addr = (uint32_t)(((kt * 104 + n) * 4 + tg) * 8
                                     + slot * 4 + o * 2);
    *(__half*)(g_Apair + addr) = __float2half(a);
}

// ---------------------------------------------------------------------------
// Kernel 2: ring-buffer persistent GEMM, fp16 m16n8k16 single-pass.
//   warp 16 = producer (tiles c -> slot c%7); groups 0..3 consume c≡g (mod 4).
// Compute core: M=32 warp tiles, permuted rows (frag f, group g -> physical
// rows (2m+f)+4g and +32), scalar-LDS a-frags packed to fp16 in-register,
// paired-B LDS.64, staged TMA epilogue.
// ---------------------------------------------------------------------------
extern __shared__ unsigned char smem[];

__global__ void __launch_bounds__(NTHR, 1)
fourier_mma_kernel(const float* __restrict__ x, float* __restrict__ out,
                   int ntiles) {
    const int tid   = threadIdx.x;
    const int wid   = tid >> 5;       // 0..16
    const int grp   = tid >> 7;       // 0..3 consumers, 4 producer
    const int gtid  = tid & 127;
    const int w4    = (tid >> 5) & 3;
    const int lane  = tid & 31;
    const int g     = lane >> 2;
    const int tg    = lane & 3;
    const int mwarp = w4 >> 1;
    const int nhalf = w4 & 1;
    const int NT    = nhalf ? 6 : 7;
    const uint32_t sbase = smem_u32(smem);
    const uint32_t mbF = sbase + MBAR_OFF;        // full[7]
    const uint32_t mbE = sbase + MBAR_OFF + 56;   // empty[7]
    const uint32_t mbA = sbase + MBAR_OFF + 112;

    const int climit = (ntiles - (int)blockIdx.x + GRID - 1) / GRID;

    // zero-fill all slots + pad (finite data everywhere before first MMA)
    for (int i = tid; i < (NSLOT * TILE_BYTES + 256) / 4; i += NTHR)
        *(uint32_t*)(smem + RAWBASE + i * 4) = 0;
    if (tid == 0) {
        #pragma unroll
        for (int i = 0; i < NSLOT; ++i) {
            mbar_init(mbF + i * 8, 1);
            mbar_init(mbE + i * 8, 1);
        }
        mbar_init(mbA, 1);
        mbar_expect_tx(mbA, A_IMG_BYTES);
        bulk_g2s(sbase + AIMG_OFF, g_Apair, A_IMG_BYTES, mbA);
    }
    __syncthreads();

    // ---- producer warp ----
    if (wid == 16) {
        if (lane == 0) {
            FENCE_ASYNC();
            const char* xb = (const char*)x + (size_t)blockIdx.x * TILE_BYTES;
            #pragma unroll 1
            for (int c = 0; c < climit; ++c) {
                const int s = c % NSLOT;
                const int k = c / NSLOT;
                if (k > 0) mbar_wait(mbE + s * 8, (uint32_t)((k - 1) & 1));
                mbar_expect_tx(mbF + s * 8, TILE_BYTES);
                bulk_g2s(sbase + RAWBASE + (uint32_t)s * TILE_BYTES,
                         xb + (size_t)c * (GRID * TILE_BYTES),
                         TILE_BYTES, mbF + s * 8);
            }
        }
        return;
    }

    // ---- consumers ----
    mbar_wait(mbA, 0);

    // a-frag bases: frag f, physical row (2m+f)+4g, k byte offset 2tg*4
    const uint32_t ra0 = (uint32_t)(((2 * mwarp + 0) + 4 * g) * DD + 2 * tg) * 4u;
    const uint32_t ra1 = (uint32_t)(((2 * mwarp + 1) + 4 * g) * DD + 2 * tg) * 4u;
    // b pair base: [kt=0][n = nhalf*56 + g][tg] (8B entries)
    const uint32_t rbA = sbase + AIMG_OFF
        + (uint32_t)(((nhalf * 56 + g) * 4 + tg) * 8);
    const int barid = grp + 1;

    #pragma unroll 1
    for (int c = grp; c < climit; c += NGRP) {
        const int s = c % NSLOT;
        const int k = c / NSLOT;
        mbar_wait(mbF + s * 8, (uint32_t)(k & 1));

        float acc[2][7][4];
        #pragma unroll
        for (int f = 0; f < 2; ++f)
            #pragma unroll
            for (int nt = 0; nt < 7; ++nt)
                #pragma unroll
                for (int i = 0; i < 4; ++i) acc[f][nt][i] = 0.0f;

        const uint32_t rawb = sbase + RAWBASE + (uint32_t)s * TILE_BYTES;
        const uint32_t rx0 = rawb + ra0;
        const uint32_t rx1 = rawb + ra1;

        #pragma unroll
        for (int kt = 0; kt < 7; ++kt) {
            const uint32_t ko = (uint32_t)kt * 64u;   // 16 k-words
            // a-frags: regs = pack(k, k+1) at (row, 2tg), (row+8 ...), (k+8 ...)
            uint32_t a0[4], a1[4];
            {
                const uint32_t p = rx0 + ko;
                a0[0] = pack_h2(ldsf(p),               ldsf(p + 4));
                a0[1] = pack_h2(ldsf(p + 12928),       ldsf(p + 12932));   // +32 rows
                a0[2] = pack_h2(ldsf(p + 32),          ldsf(p + 36));      // +8 k
                a0[3] = pack_h2(ldsf(p + 12960),       ldsf(p + 12964));
            }
            {
                const uint32_t p = rx1 + ko;
                a1[0] = pack_h2(ldsf(p),               ldsf(p + 4));
                a1[1] = pack_h2(ldsf(p + 12928),       ldsf(p + 12932));
                a1[2] = pack_h2(ldsf(p + 32),          ldsf(p + 36));
                a1[3] = pack_h2(ldsf(p + 12960),       ldsf(p + 12964));
            }

            const uint32_t kb = rbA + (uint32_t)kt * 3328u;   // 104*4*8
            uint32_t b[7][2];
            #pragma unroll
            for (int nt = 0; nt < 7; ++nt)
                if (nt < NT) ldsv2(b[nt], kb + (uint32_t)nt * 256u);

            #pragma unroll
            for (int nt = 0; nt < 7; ++nt)
                if (nt < NT) mma_f16(acc[0][nt], a0, b[nt]);
            #pragma unroll
            for (int nt = 0; nt < 7; ++nt)
                if (nt < NT) mma_f16(acc[1][nt], a1, b[nt]);
        }

        // ---- epilogue: stage [64 x 101] fp32 image back into the slot ----
        GRP_BAR(barid);
        {
            #pragma unroll
            for (int f = 0; f < 2; ++f) {
                const uint32_t st0 = rawb
                    + (uint32_t)(((2 * mwarp + f) + 4 * g) * KO) * 4u;
                #pragma unroll
                for (int nt = 0; nt < 7; ++nt) {
                    if (nt >= NT) break;
                    const int col = nhalf * 56 + nt * 8 + tg * 2;
                    if (col < KO) {
                        stsf(st0 + (uint32_t)col * 4u, acc[f][nt][0]);
                        stsf(st0 + 12928u + (uint32_t)col * 4u, acc[f][nt][2]);
                        if (col + 1 < KO) {
                            stsf(st0 + (uint32_t)(col + 1) * 4u, acc[f][nt][1]);
                            stsf(st0 + 12928u + (uint32_t)(col + 1) * 4u,
                                 acc[f][nt][3]);
                        }
                    }
                }
            }
        }
        GRP_BAR(barid);
        if (gtid == 0) {
            const int t = (int)blockIdx.x + GRID * c;
            FENCE_ASYNC();
            bulk_s2g(out + (size_t)t * (BM * KO), rawb, TILE_BYTES);
            S2G_COMMIT();
            S2G_WAIT0();
            mbar_arrive(mbE + s * 8);
        }
    }
}

// ---------------------------------------------------------------------------
// Launch
// ---------------------------------------------------------------------------
extern "C" void kernel_launch(void* const* d_in, const int* in_sizes, int n_in,
                              void* d_out, int out_size) {
    const float* x   = (const float*)d_in[0];
    const float* Wre = (const float*)d_in[1];
    const float* Wim = (const float*)d_in[2];
    float* out = (float*)d_out;

    const int B = in_sizes[0] / DD;       // 262144
    const int ntiles = B / BM;            // 4096

    build_A_kernel<<<104, KPAD2>>>(Wre, Wim);

    cudaFuncSetAttribute(fourier_mma_kernel,
                         cudaFuncAttributeMaxDynamicSharedMemorySize, SMEM_BYTES);
    fourier_mma_kernel<<<GRID, NTHR, SMEM_BYTES>>>(x, out, ntiles);
    (void)n_in; (void)out_size;
}